// round 14
// baseline (speedup 1.0000x reference)
#include <cuda_runtime.h>
#include <cuda_bf16.h>
#include <cstdint>
#include <math.h>

#define Bn 8
#define Tn 2048
#define Cn 1024
#define Hn 128
#define BT (Bn * Tn)

// bf16 hi/lo scratch (device globals, no allocation)
__device__ __nv_bfloat16 g_Qh[BT * Hn], g_Ql[BT * Hn];
__device__ __nv_bfloat16 g_Kh[BT * Hn], g_Kl[BT * Hn];
__device__ __nv_bfloat16 g_Vh[BT * Hn], g_Vl[BT * Hn];
__device__ __nv_bfloat16 g_Wh[3 * Hn * Cn], g_Wl[3 * Hn * Cn];  // [o][n][k]
__device__ __nv_bfloat16 g_Xh[BT * Cn], g_Xl[BT * Cn];          // [m][k]

// ---------------- helpers ----------------
#define SWZ(x) ((x) ^ (((x) >> 3) & 0x70))

__device__ __forceinline__ uint32_t smem_u32(const void* p) {
    uint32_t a;
    asm("{ .reg .u64 t; cvta.to.shared.u64 t, %1; cvt.u32.u64 %0, t; }" : "=r"(a) : "l"(p));
    return a;
}
__device__ __forceinline__ uint32_t pack2(float lo, float hi) {
    uint32_t r;
    asm("cvt.rn.bf16x2.f32 %0, %1, %2;" : "=r"(r) : "f"(hi), "f"(lo));
    return r;
}
__device__ __forceinline__ void split2(float a, float b, uint32_t& h, uint32_t& l) {
    float ah = __bfloat162float(__float2bfloat16(a));
    float bh = __bfloat162float(__float2bfloat16(b));
    h = pack2(ah, bh);
    l = pack2(a - ah, b - bh);
}
__device__ __forceinline__ void ldsm4(uint32_t* r, uint32_t addr) {
    asm volatile("ldmatrix.sync.aligned.m8n8.x4.shared.b16 {%0,%1,%2,%3}, [%4];"
                 : "=r"(r[0]), "=r"(r[1]), "=r"(r[2]), "=r"(r[3]) : "r"(addr));
}
__device__ __forceinline__ void ldsm4t(uint32_t* r, uint32_t addr) {
    asm volatile("ldmatrix.sync.aligned.m8n8.x4.trans.shared.b16 {%0,%1,%2,%3}, [%4];"
                 : "=r"(r[0]), "=r"(r[1]), "=r"(r[2]), "=r"(r[3]) : "r"(addr));
}
__device__ __forceinline__ void mma_bf16(float* d, const uint32_t* a, uint32_t b0, uint32_t b1) {
    asm volatile("mma.sync.aligned.m16n8k16.row.col.f32.bf16.bf16.f32 "
                 "{%0,%1,%2,%3}, {%4,%5,%6,%7}, {%8,%9}, {%0,%1,%2,%3};"
                 : "+f"(d[0]), "+f"(d[1]), "+f"(d[2]), "+f"(d[3])
                 : "r"(a[0]), "r"(a[1]), "r"(a[2]), "r"(a[3]), "r"(b0), "r"(b1));
}
__device__ __forceinline__ uint32_t aAddr(uint32_t base, int r0, int bc, int lane) {
    int r = r0 + (lane & 15);
    int c = bc + ((lane >> 4) << 4);
    return base + SWZ((uint32_t)(r * 128 + c));
}
__device__ __forceinline__ uint32_t bAddr(uint32_t base, int n0, int bc, int lane) {
    int r = n0 + (lane & 7) + ((lane >> 4) << 3);
    int c = bc + (((lane >> 3) & 1) << 4);
    return base + SWZ((uint32_t)(r * 128 + c));
}
// B-operand x4 via trans from row-major V[k][n], 32-row tile, 4KB col-blocks
__device__ __forceinline__ uint32_t vAddr32(uint32_t base, int n0, int k0, int lane) {
    int g = lane >> 3, li = lane & 7;
    int kr = k0 + ((g & 1) << 3) + li;
    int nc = n0 + ((g >> 1) << 3);
    return base + ((uint32_t)(nc >> 6) << 12) + SWZ((uint32_t)(kr * 128 + (nc & 63) * 2));
}
__device__ __forceinline__ void cpa16(uint32_t dst, const void* src) {
    asm volatile("cp.async.cg.shared.global [%0], [%1], 16;" :: "r"(dst), "l"(src));
}
#define CPA_COMMIT() asm volatile("cp.async.commit_group;" ::: "memory")
#define CPA_WAIT(n)  asm volatile("cp.async.wait_group %0;" :: "n"(n) : "memory")

// ============================================================================
// convW / convX (restored R11 versions)
// ============================================================================
__global__ void convW(const float* __restrict__ Wq, const float* __restrict__ Wk,
                      const float* __restrict__ Wv) {
    int idx = blockIdx.x * 256 + threadIdx.x;
    int o = idx >> 17, rem = idx & 131071;
    int k = rem >> 7, n = rem & 127;
    const float* W = o == 0 ? Wq : o == 1 ? Wk : Wv;
    float f = W[(size_t)k * Hn + n];
    __nv_bfloat16 h = __float2bfloat16(f);
    size_t dst = ((size_t)o * Hn + n) * Cn + k;
    g_Wh[dst] = h;
    g_Wl[dst] = __float2bfloat16(f - __bfloat162float(h));
}
__global__ void convX(const float* __restrict__ x) {
    size_t idx = (size_t)blockIdx.x * 256 + threadIdx.x;   // over BT*Cn/2
    float2 v = *(const float2*)(x + 2 * idx);
    uint32_t h, l;
    split2(v.x, v.y, h, l);
    *(uint32_t*)((char*)g_Xh + 4 * idx) = h;
    *(uint32_t*)((char*)g_Xl + 4 * idx) = l;
}

// ============================================================================
// Projection: restored R10/R11 version (512 thr, fused 3-product, occ 1)
// ============================================================================
#define PJ_SMEM (131072 + 128)

__device__ __forceinline__ void pj_stage(uint32_t sb, int m0, int o, int kc, int tid) {
    uint32_t stg = sb + (uint32_t)(kc & 1) * 65536u;
    #pragma unroll
    for (int arr = 0; arr < 4; arr++) {
        const __nv_bfloat16* src =
            arr == 0 ? g_Xh : arr == 1 ? g_Xl : arr == 2 ? g_Wh : g_Wl;
        uint32_t dbase = stg + (uint32_t)arr * 16384u;
        #pragma unroll
        for (int i = 0; i < 2; i++) {
            int id = tid * 2 + i;                 // 0..1023
            int row = id >> 3, c = id & 7;        // 128 rows x 8 chunks
            size_t g = (arr < 2)
                ? ((size_t)(m0 + row) * Cn + kc * 64 + c * 8)
                : (((size_t)o * Hn + row) * Cn + kc * 64 + c * 8);
            cpa16(dbase + SWZ((uint32_t)(row * 128 + c * 16)), src + g);
        }
    }
}

__global__ __launch_bounds__(512, 1) void proj_mma(void) {
    extern __shared__ char smraw[];
    char* sm = (char*)(((uintptr_t)smraw + 127) & ~(uintptr_t)127);
    const uint32_t sb = smem_u32(sm);
    const int tid = threadIdx.x, lane = tid & 31, wid = tid >> 5;
    const int mw = wid >> 2, nww = wid & 3;
    const int m0 = blockIdx.x * 128, o = blockIdx.y;

    float d[2][4][4];
    #pragma unroll
    for (int i = 0; i < 2; i++)
        #pragma unroll
        for (int j = 0; j < 4; j++)
            #pragma unroll
            for (int e = 0; e < 4; e++) d[i][j][e] = 0.0f;

    pj_stage(sb, m0, o, 0, tid);
    CPA_COMMIT();

    for (int kc = 0; kc < 16; kc++) {
        if (kc + 1 < 16) { pj_stage(sb, m0, o, kc + 1, tid); CPA_COMMIT(); CPA_WAIT(1); }
        else CPA_WAIT(0);
        __syncthreads();

        const uint32_t stg = sb + (uint32_t)(kc & 1) * 65536u;
        #pragma unroll
        for (int kk = 0; kk < 4; kk++) {
            int bc = kk * 32;
            uint32_t aH[2][4], aL[2][4];
            #pragma unroll
            for (int mt = 0; mt < 2; mt++) {
                ldsm4(aH[mt], aAddr(stg, mw * 32 + mt * 16, bc, lane));
                ldsm4(aL[mt], aAddr(stg + 16384u, mw * 32 + mt * 16, bc, lane));
            }
            #pragma unroll
            for (int p2 = 0; p2 < 2; p2++) {
                uint32_t bH[4], bL[4];
                ldsm4(bH, bAddr(stg + 32768u, nww * 32 + p2 * 16, bc, lane));
                ldsm4(bL, bAddr(stg + 49152u, nww * 32 + p2 * 16, bc, lane));
                #pragma unroll
                for (int mt = 0; mt < 2; mt++) {
                    float* d0 = d[mt][p2 * 2];
                    float* d1 = d[mt][p2 * 2 + 1];
                    mma_bf16(d0, aH[mt], bH[0], bH[1]);
                    mma_bf16(d1, aH[mt], bH[2], bH[3]);
                    mma_bf16(d0, aL[mt], bH[0], bH[1]);
                    mma_bf16(d1, aL[mt], bH[2], bH[3]);
                    mma_bf16(d0, aH[mt], bL[0], bL[1]);
                    mma_bf16(d1, aH[mt], bL[2], bL[3]);
                }
            }
        }
        __syncthreads();
    }

    __nv_bfloat16* oh = o == 0 ? g_Qh : o == 1 ? g_Kh : g_Vh;
    __nv_bfloat16* ol = o == 0 ? g_Ql : o == 1 ? g_Kl : g_Vl;
    const int rq = lane >> 2, cq = (lane & 3) * 2;
    #pragma unroll
    for (int mt = 0; mt < 2; mt++)
        #pragma unroll
        for (int h = 0; h < 2; h++) {
            int r = m0 + mw * 32 + mt * 16 + rq + h * 8;
            #pragma unroll
            for (int nt = 0; nt < 4; nt++) {
                int c = nww * 32 + nt * 8 + cq;
                uint32_t hw, lw;
                split2(d[mt][nt][h * 2], d[mt][nt][h * 2 + 1], hw, lw);
                size_t byt = ((size_t)r * Hn + c) * 2;
                *(uint32_t*)((char*)oh + byt) = hw;
                *(uint32_t*)((char*)ol + byt) = lw;
            }
        }
}

// ============================================================================
// Attention v3: 128 thr, 4 warps (16 q-rows each, fully independent —
// no cross-warp reductions). 64-row q-tile per CTA, 32-key tiles double-
// buffered. smem 96KB -> 2 CTAs/SM (decorrelated phases). Grid (32, 8).
// smem: QH 0 (2x8K halves), QL 16K | stages 32K,64K:
//       {KH +0 (2x4K halves), KL +8K, VH +16K, VL +24K}
// ============================================================================
#define AT_STG0 32768u
#define AT_SMEM (98304 + 128)

__device__ __forceinline__ void at_stage(uint32_t sb, int b, int t, int s, int tid) {
    uint32_t stg = sb + AT_STG0 + (uint32_t)s * 32768u;
    #pragma unroll
    for (int arr = 0; arr < 4; arr++) {
        const __nv_bfloat16* src =
            arr == 0 ? g_Kh : arr == 1 ? g_Kl : arr == 2 ? g_Vh : g_Vl;
        uint32_t dbase = stg + (uint32_t)arr * 8192u;
        #pragma unroll
        for (int i = 0; i < 4; i++) {
            int id = tid * 4 + i;                 // 0..511
            int row = id >> 4, c = id & 15;       // 32 rows x 16 chunks
            size_t g = (size_t)(b * Tn + t * 32 + row) * Hn + c * 8;
            uint32_t dst = dbase + ((c >= 8) ? 4096u : 0u)
                         + SWZ((uint32_t)(row * 128 + (c & 7) * 16));
            cpa16(dst, src + g);
        }
    }
}

__global__ __launch_bounds__(128, 2) void attn_mma(float* __restrict__ out) {
    extern __shared__ char smraw[];
    char* sm = (char*)(((uintptr_t)smraw + 127) & ~(uintptr_t)127);
    const uint32_t sb = smem_u32(sm);
    const int tid = threadIdx.x, lane = tid & 31, wid = tid >> 5;
    const int rq = lane >> 2, cq = (lane & 3) * 2;
    const int b = blockIdx.y, qt = blockIdx.x;
    const int q0 = qt * 64;
    const int ntiles = (qt + 1) * 2;              // 32-key tiles

    const float scale = 0.08838834764831845f;     // 1/sqrt(128)

    at_stage(sb, b, 0, 0, tid);
    CPA_COMMIT();

    // stage Q hi/lo (64 rows): 2048 16B lines, 16 per thread
    #pragma unroll
    for (int i = 0; i < 16; i++) {
        int id = tid * 16 + i;                    // 0..2047
        int arr = id >> 10, rem = id & 1023;
        int row = rem >> 4, c = rem & 15;
        const __nv_bfloat16* src = (arr ? g_Ql : g_Qh);
        uint4 v = *(const uint4*)(src + (size_t)(b * Tn + q0 + row) * Hn + c * 8);
        *(uint4*)(sm + arr * 16384 + ((c >= 8) ? 8192 : 0)
                  + SWZ((uint32_t)(row * 128 + (c & 7) * 16))) = v;
    }

    float o[16][4];
    #pragma unroll
    for (int j = 0; j < 16; j++)
        #pragma unroll
        for (int e = 0; e < 4; e++) o[j][e] = 0.0f;
    float rs[2] = { 0.0f, 0.0f };

    #pragma unroll 1
    for (int t = 0; t < ntiles; t++) {
        CPA_WAIT(0);
        __syncthreads();            // stage visible + prev buffer consumers done
        if (t + 1 < ntiles) {
            at_stage(sb, b, t + 1, (t + 1) & 1, tid);
            CPA_COMMIT();
        }
        const uint32_t stg = sb + AT_STG0 + (uint32_t)(t & 1) * 32768u;

        // ---- S = Q K^T : 16 rows x 32 keys, 3 accumulator sets ----
        float shh[4][4], slh[4][4], shl[4][4];
        #pragma unroll
        for (int g = 0; g < 4; g++)
            #pragma unroll
            for (int e = 0; e < 4; e++) { shh[g][e] = 0.f; slh[g][e] = 0.f; shl[g][e] = 0.f; }

        #pragma unroll
        for (int kk = 0; kk < 8; kk++) {
            uint32_t qh = (uint32_t)(kk >> 2) * 8192u;  // Q col-block
            uint32_t kh = (uint32_t)(kk >> 2) * 4096u;  // K col-block
            int bc = (kk & 3) * 32;
            uint32_t aH[4], aL[4], bHa[4], bHb[4], bLa[4], bLb[4];
            ldsm4(aH,  aAddr(sb + qh,           wid * 16, bc, lane));
            ldsm4(aL,  aAddr(sb + 16384u + qh,  wid * 16, bc, lane));
            ldsm4(bHa, bAddr(stg + kh,          0,  bc, lane));
            ldsm4(bHb, bAddr(stg + kh,          16, bc, lane));
            ldsm4(bLa, bAddr(stg + 8192u + kh,  0,  bc, lane));
            ldsm4(bLb, bAddr(stg + 8192u + kh,  16, bc, lane));
            mma_bf16(shh[0], aH, bHa[0], bHa[1]);
            mma_bf16(shh[1], aH, bHa[2], bHa[3]);
            mma_bf16(shh[2], aH, bHb[0], bHb[1]);
            mma_bf16(shh[3], aH, bHb[2], bHb[3]);
            mma_bf16(slh[0], aL, bHa[0], bHa[1]);
            mma_bf16(slh[1], aL, bHa[2], bHa[3]);
            mma_bf16(slh[2], aL, bHb[0], bHb[1]);
            mma_bf16(slh[3], aL, bHb[2], bHb[3]);
            mma_bf16(shl[0], aH, bLa[0], bLa[1]);
            mma_bf16(shl[1], aH, bLa[2], bLa[3]);
            mma_bf16(shl[2], aH, bLb[0], bLb[1]);
            mma_bf16(shl[3], aH, bLb[2], bLb[3]);
        }

        // ---- softmax in registers (max-free) ----
        float pr[4][4];
        const int lim0 = q0 + wid * 16 + rq;
        const int lim1 = lim0 + 8;
        #pragma unroll
        for (int g = 0; g < 4; g++) {
            int j = t * 32 + g * 8 + cq;
            float z0 = shh[g][0] + slh[g][0] + shl[g][0];
            float z1 = shh[g][1] + slh[g][1] + shl[g][1];
            float z2 = shh[g][2] + slh[g][2] + shl[g][2];
            float z3 = shh[g][3] + slh[g][3] + shl[g][3];
            float p0 = (j     <= lim0) ? __expf(z0 * scale) : 0.0f;
            float p1 = (j + 1 <= lim0) ? __expf(z1 * scale) : 0.0f;
            float p2 = (j     <= lim1) ? __expf(z2 * scale) : 0.0f;
            float p3 = (j + 1 <= lim1) ? __expf(z3 * scale) : 0.0f;
            pr[g][0] = p0; pr[g][1] = p1; pr[g][2] = p2; pr[g][3] = p3;
            rs[0] += p0 + p1;
            rs[1] += p2 + p3;
        }
        uint32_t aPh[2][4], aPl[2][4];
        #pragma unroll
        for (int kg = 0; kg < 2; kg++) {
            split2(pr[2 * kg][0],     pr[2 * kg][1],     aPh[kg][0], aPl[kg][0]);
            split2(pr[2 * kg][2],     pr[2 * kg][3],     aPh[kg][1], aPl[kg][1]);
            split2(pr[2 * kg + 1][0], pr[2 * kg + 1][1], aPh[kg][2], aPl[kg][2]);
            split2(pr[2 * kg + 1][2], pr[2 * kg + 1][3], aPh[kg][3], aPl[kg][3]);
        }

        // ---- O += P V over all 128 h-cols (warp-private O) ----
        #pragma unroll
        for (int kg = 0; kg < 2; kg++) {
            #pragma unroll
            for (int hb = 0; hb < 8; hb++) {
                uint32_t bH[4], bL[4];
                ldsm4t(bH, vAddr32(stg + 16384u, hb * 16, kg * 16, lane));
                ldsm4t(bL, vAddr32(stg + 24576u, hb * 16, kg * 16, lane));
                mma_bf16(o[2 * hb],     aPh[kg], bH[0], bH[1]);
                mma_bf16(o[2 * hb + 1], aPh[kg], bH[2], bH[3]);
                mma_bf16(o[2 * hb],     aPl[kg], bH[0], bH[1]);
                mma_bf16(o[2 * hb + 1], aPl[kg], bH[2], bH[3]);
                mma_bf16(o[2 * hb],     aPh[kg], bL[0], bL[1]);
                mma_bf16(o[2 * hb + 1], aPh[kg], bL[2], bL[3]);
            }
        }
    }

    // ---- epilogue: warp-local row sums, normalize, write fp32 ----
    float r0 = rs[0];
    r0 += __shfl_xor_sync(0xffffffffu, r0, 1);
    r0 += __shfl_xor_sync(0xffffffffu, r0, 2);
    float r1 = rs[1];
    r1 += __shfl_xor_sync(0xffffffffu, r1, 1);
    r1 += __shfl_xor_sync(0xffffffffu, r1, 2);
    const float inv0 = 1.0f / r0;
    const float inv1 = 1.0f / r1;

    float* op = out + ((size_t)(b * Tn + q0 + wid * 16)) * Hn;
    #pragma unroll
    for (int j = 0; j < 16; j++) {
        int col = (j >> 1) * 16 + (j & 1) * 8 + cq;
        *(float2*)(op + (size_t)rq * Hn + col) =
            make_float2(o[j][0] * inv0, o[j][1] * inv0);
        *(float2*)(op + (size_t)(rq + 8) * Hn + col) =
            make_float2(o[j][2] * inv1, o[j][3] * inv1);
    }
}

extern "C" void kernel_launch(void* const* d_in, const int* in_sizes, int n_in,
                              void* d_out, int out_size)
{
    const float* x  = (const float*)d_in[0];
    const float* Wq = (const float*)d_in[1];
    const float* Wk = (const float*)d_in[2];
    const float* Wv = (const float*)d_in[3];
    float* out = (float*)d_out;

    cudaFuncSetAttribute(proj_mma, cudaFuncAttributeMaxDynamicSharedMemorySize, PJ_SMEM);
    cudaFuncSetAttribute(attn_mma, cudaFuncAttributeMaxDynamicSharedMemorySize, AT_SMEM);

    convW<<<1536, 256>>>(Wq, Wk, Wv);
    convX<<<BT * Cn / 512, 256>>>(x);
    proj_mma<<<dim3(BT / 128, 3), 512, PJ_SMEM>>>();
    attn_mma<<<dim3(32, Bn), 128, AT_SMEM>>>(out);
}

// round 15
// speedup vs baseline: 1.1251x; 1.1251x over previous
#include <cuda_runtime.h>
#include <cuda_bf16.h>
#include <cstdint>
#include <math.h>

#define Bn 8
#define Tn 2048
#define Cn 1024
#define Hn 128
#define BT (Bn * Tn)

// bf16 hi/lo scratch (device globals, no allocation)
__device__ __nv_bfloat16 g_Qh[BT * Hn], g_Ql[BT * Hn];
__device__ __nv_bfloat16 g_Kh[BT * Hn], g_Kl[BT * Hn];
__device__ __nv_bfloat16 g_Vh[BT * Hn], g_Vl[BT * Hn];
__device__ __nv_bfloat16 g_Wh[3 * Hn * Cn], g_Wl[3 * Hn * Cn];  // [o][n][k]
__device__ __nv_bfloat16 g_Xh[BT * Cn], g_Xl[BT * Cn];          // [m][k]

// ---------------- helpers ----------------
#define SWZ(x) ((x) ^ (((x) >> 3) & 0x70))

__device__ __forceinline__ uint32_t smem_u32(const void* p) {
    uint32_t a;
    asm("{ .reg .u64 t; cvta.to.shared.u64 t, %1; cvt.u32.u64 %0, t; }" : "=r"(a) : "l"(p));
    return a;
}
__device__ __forceinline__ uint32_t pack2(float lo, float hi) {
    uint32_t r;
    asm("cvt.rn.bf16x2.f32 %0, %1, %2;" : "=r"(r) : "f"(hi), "f"(lo));
    return r;
}
__device__ __forceinline__ void split2(float a, float b, uint32_t& h, uint32_t& l) {
    float ah = __bfloat162float(__float2bfloat16(a));
    float bh = __bfloat162float(__float2bfloat16(b));
    h = pack2(ah, bh);
    l = pack2(a - ah, b - bh);
}
__device__ __forceinline__ void ldsm4(uint32_t* r, uint32_t addr) {
    asm volatile("ldmatrix.sync.aligned.m8n8.x4.shared.b16 {%0,%1,%2,%3}, [%4];"
                 : "=r"(r[0]), "=r"(r[1]), "=r"(r[2]), "=r"(r[3]) : "r"(addr));
}
__device__ __forceinline__ void ldsm4t(uint32_t* r, uint32_t addr) {
    asm volatile("ldmatrix.sync.aligned.m8n8.x4.trans.shared.b16 {%0,%1,%2,%3}, [%4];"
                 : "=r"(r[0]), "=r"(r[1]), "=r"(r[2]), "=r"(r[3]) : "r"(addr));
}
__device__ __forceinline__ void mma_bf16(float* d, const uint32_t* a, uint32_t b0, uint32_t b1) {
    asm volatile("mma.sync.aligned.m16n8k16.row.col.f32.bf16.bf16.f32 "
                 "{%0,%1,%2,%3}, {%4,%5,%6,%7}, {%8,%9}, {%0,%1,%2,%3};"
                 : "+f"(d[0]), "+f"(d[1]), "+f"(d[2]), "+f"(d[3])
                 : "r"(a[0]), "r"(a[1]), "r"(a[2]), "r"(a[3]), "r"(b0), "r"(b1));
}
__device__ __forceinline__ uint32_t aAddr(uint32_t base, int r0, int bc, int lane) {
    int r = r0 + (lane & 15);
    int c = bc + ((lane >> 4) << 4);
    return base + SWZ((uint32_t)(r * 128 + c));
}
__device__ __forceinline__ uint32_t bAddr(uint32_t base, int n0, int bc, int lane) {
    int r = n0 + (lane & 7) + ((lane >> 4) << 3);
    int c = bc + (((lane >> 3) & 1) << 4);
    return base + SWZ((uint32_t)(r * 128 + c));
}
// B-operand x4 via trans from row-major V[k][n]: two 8K col-blocks (n>=64)
__device__ __forceinline__ uint32_t vAddr(uint32_t base, int n0, int k0, int lane) {
    int g = lane >> 3, li = lane & 7;
    int kr = k0 + ((g & 1) << 3) + li;
    int nc = n0 + ((g >> 1) << 3);
    return base + ((uint32_t)(nc >> 6) << 13) + SWZ((uint32_t)(kr * 128 + (nc & 63) * 2));
}
__device__ __forceinline__ void cpa16(uint32_t dst, const void* src) {
    asm volatile("cp.async.cg.shared.global [%0], [%1], 16;" :: "r"(dst), "l"(src));
}
#define CPA_COMMIT() asm volatile("cp.async.commit_group;" ::: "memory")
#define CPA_WAIT(n)  asm volatile("cp.async.wait_group %0;" :: "n"(n) : "memory")

// ============================================================================
// convW / convX
// ============================================================================
__global__ void convW(const float* __restrict__ Wq, const float* __restrict__ Wk,
                      const float* __restrict__ Wv) {
    int idx = blockIdx.x * 256 + threadIdx.x;
    int o = idx >> 17, rem = idx & 131071;
    int k = rem >> 7, n = rem & 127;
    const float* W = o == 0 ? Wq : o == 1 ? Wk : Wv;
    float f = W[(size_t)k * Hn + n];
    __nv_bfloat16 h = __float2bfloat16(f);
    size_t dst = ((size_t)o * Hn + n) * Cn + k;
    g_Wh[dst] = h;
    g_Wl[dst] = __float2bfloat16(f - __bfloat162float(h));
}
__global__ void convX(const float* __restrict__ x) {
    size_t idx = (size_t)blockIdx.x * 256 + threadIdx.x;   // over BT*Cn/2
    float2 v = *(const float2*)(x + 2 * idx);
    uint32_t h, l;
    split2(v.x, v.y, h, l);
    *(uint32_t*)((char*)g_Xh + 4 * idx) = h;
    *(uint32_t*)((char*)g_Xl + 4 * idx) = l;
}

// ============================================================================
// Projection v2: grid (BT/64, 3) = (256, 3), 256 thr (8 warps = 2mw x 4nw,
// warp tile 32 rows x 32 cols), 64-row M-tiles, k-chunks of 64,
// cp.async double-buffered, occ 2 CTAs/SM (phase decorrelation).
// Stage (48KB): XH 0 (8K), XL 8K, WH 16K (16K), WL 32K (16K). Two stages.
// ============================================================================
#define PJ_STGSZ 49152u
#define PJ_SMEM  (2 * 49152 + 128)

__device__ __forceinline__ void pj_stage(uint32_t sb, int m0, int o, int kc, int tid) {
    uint32_t stg = sb + (uint32_t)(kc & 1) * PJ_STGSZ;
    // x tile: 64 rows x 64 k (hi, lo)
    #pragma unroll
    for (int arr = 0; arr < 2; arr++) {
        const __nv_bfloat16* src = arr ? g_Xl : g_Xh;
        uint32_t dbase = stg + (uint32_t)arr * 8192u;
        #pragma unroll
        for (int i = 0; i < 2; i++) {
            int id = tid * 2 + i;                 // 0..511
            int row = id >> 3, c = id & 7;        // 64 rows x 8 chunks
            cpa16(dbase + SWZ((uint32_t)(row * 128 + c * 16)),
                  src + (size_t)(m0 + row) * Cn + kc * 64 + c * 8);
        }
    }
    // W tile: 128 n-rows x 64 k (hi, lo)
    #pragma unroll
    for (int arr = 0; arr < 2; arr++) {
        const __nv_bfloat16* src = arr ? g_Wl : g_Wh;
        uint32_t dbase = stg + 16384u + (uint32_t)arr * 16384u;
        #pragma unroll
        for (int i = 0; i < 4; i++) {
            int id = tid * 4 + i;                 // 0..1023
            int row = id >> 3, c = id & 7;        // 128 rows x 8 chunks
            cpa16(dbase + SWZ((uint32_t)(row * 128 + c * 16)),
                  src + ((size_t)o * Hn + row) * Cn + kc * 64 + c * 8);
        }
    }
}

__global__ __launch_bounds__(256, 2) void proj_mma(void) {
    extern __shared__ char smraw[];
    char* sm = (char*)(((uintptr_t)smraw + 127) & ~(uintptr_t)127);
    const uint32_t sb = smem_u32(sm);
    const int tid = threadIdx.x, lane = tid & 31, wid = tid >> 5;
    const int mw = wid >> 2, nw = wid & 3;        // 2 m-warps x 4 n-warps
    const int m0 = blockIdx.x * 64, o = blockIdx.y;

    float d[2][4][4];                             // [mt][j: (g<<1)|b][elem]
    #pragma unroll
    for (int i = 0; i < 2; i++)
        #pragma unroll
        for (int j = 0; j < 4; j++)
            #pragma unroll
            for (int e = 0; e < 4; e++) d[i][j][e] = 0.0f;

    pj_stage(sb, m0, o, 0, tid);
    CPA_COMMIT();

    for (int kc = 0; kc < 16; kc++) {
        if (kc + 1 < 16) { pj_stage(sb, m0, o, kc + 1, tid); CPA_COMMIT(); CPA_WAIT(1); }
        else CPA_WAIT(0);
        __syncthreads();

        const uint32_t stg = sb + (uint32_t)(kc & 1) * PJ_STGSZ;
        const uint32_t xh = stg, xl = stg + 8192u;
        const uint32_t wh = stg + 16384u, wl = stg + 32768u;
        #pragma unroll
        for (int kk = 0; kk < 4; kk++) {
            int bc = kk * 32;
            uint32_t aH[2][4], aL[2][4];
            #pragma unroll
            for (int mt = 0; mt < 2; mt++) {
                ldsm4(aH[mt], aAddr(xh, mw * 32 + mt * 16, bc, lane));
                ldsm4(aL[mt], aAddr(xl, mw * 32 + mt * 16, bc, lane));
            }
            #pragma unroll
            for (int g = 0; g < 2; g++) {
                uint32_t bH[4], bL[4];
                ldsm4(bH, bAddr(wh, nw * 32 + g * 16, bc, lane));
                ldsm4(bL, bAddr(wl, nw * 32 + g * 16, bc, lane));
                #pragma unroll
                for (int mt = 0; mt < 2; mt++) {
                    float* d0 = d[mt][g * 2];       // cols nw*32 + g*16 + 0..7
                    float* d1 = d[mt][g * 2 + 1];   // cols nw*32 + g*16 + 8..15
                    mma_bf16(d0, aH[mt], bH[0], bH[1]);
                    mma_bf16(d1, aH[mt], bH[2], bH[3]);
                    mma_bf16(d0, aL[mt], bH[0], bH[1]);
                    mma_bf16(d1, aL[mt], bH[2], bH[3]);
                    mma_bf16(d0, aH[mt], bL[0], bL[1]);
                    mma_bf16(d1, aH[mt], bL[2], bL[3]);
                }
            }
        }
        __syncthreads();
    }

    // epilogue: rows m0 + mw*32 + mt*16 + rq + h*8; cols nw*32 + (j>>1)*16 + (j&1)*8 + cq
    __nv_bfloat16* oh = o == 0 ? g_Qh : o == 1 ? g_Kh : g_Vh;
    __nv_bfloat16* ol = o == 0 ? g_Ql : o == 1 ? g_Kl : g_Vl;
    const int rq = lane >> 2, cq = (lane & 3) * 2;
    #pragma unroll
    for (int mt = 0; mt < 2; mt++)
        #pragma unroll
        for (int h = 0; h < 2; h++) {
            int r = m0 + mw * 32 + mt * 16 + rq + h * 8;
            #pragma unroll
            for (int j = 0; j < 4; j++) {
                int c = nw * 32 + (j >> 1) * 16 + (j & 1) * 8 + cq;
                uint32_t hw, lw;
                split2(d[mt][j][h * 2], d[mt][j][h * 2 + 1], hw, lw);
                size_t byt = ((size_t)r * Hn + c) * 2;
                *(uint32_t*)((char*)oh + byt) = hw;
                *(uint32_t*)((char*)ol + byt) = lw;
            }
        }
}

// ============================================================================
// Attention: EXACT R11 kernel (FA2-style reg-P, 256 thr, diagonal pairing,
// 136.2us measured) — reverted from the R14 experiment.
// ============================================================================
#define AT_STG0  32768
#define AT_OPART 163840
#define AT_LPART 196608
#define AT_SMEM  (196608 + 256 + 128)

__device__ __forceinline__ void at_stage(uint32_t sb, int b, int t, int s, int tid) {
    uint32_t stg = sb + AT_STG0 + (uint32_t)s * 65536u;
    #pragma unroll
    for (int arr = 0; arr < 4; arr++) {
        const __nv_bfloat16* src =
            arr == 0 ? g_Kh : arr == 1 ? g_Kl : arr == 2 ? g_Vh : g_Vl;
        uint32_t dbase = stg + (uint32_t)arr * 16384u;
        #pragma unroll
        for (int i = 0; i < 4; i++) {
            int id = tid * 4 + i;                 // 0..1023
            int row = id >> 4, c = id & 15;       // 64 rows x 16 chunks
            size_t g = (size_t)(b * Tn + t * 64 + row) * Hn + c * 8;
            uint32_t dst = dbase + ((c >= 8) ? 8192u : 0u)
                         + SWZ((uint32_t)(row * 128 + (c & 7) * 16));
            cpa16(dst, src + g);
        }
    }
}

__global__ __launch_bounds__(256, 1) void attn_mma(float* __restrict__ out) {
    extern __shared__ char smraw[];
    char* sm = (char*)(((uintptr_t)smraw + 127) & ~(uintptr_t)127);
    const uint32_t sb = smem_u32(sm);
    float* lpart = (float*)(sm + AT_LPART);
    const int tid = threadIdx.x, lane = tid & 31, wid = tid >> 5;
    const int mw = wid >> 1, nw = wid & 1;
    const int rq = lane >> 2, cq = (lane & 3) * 2;
    const int b = blockIdx.y;
    const int qt[2] = { (int)blockIdx.x, 31 - (int)blockIdx.x };

    const float scale = 0.08838834764831845f;  // 1/sqrt(128)

    at_stage(sb, b, 0, 0, tid);   // prefetch (seg0, tile0)
    CPA_COMMIT();

    int gi = 0;
    #pragma unroll 1
    for (int seg = 0; seg < 2; seg++) {
        const int q0 = qt[seg] * 64;
        const int nseg = qt[seg] + 1;

        // stage Q hi/lo
        #pragma unroll
        for (int i = 0; i < 8; i++) {
            int id = tid * 8 + i;                 // 0..2047
            int arr = id >> 10, rem = id & 1023;
            int row = rem >> 4, c = rem & 15;
            int half = c >> 3;
            const __nv_bfloat16* src = (arr ? g_Ql : g_Qh);
            uint4 v = *(const uint4*)(src + (size_t)(b * Tn + q0 + row) * Hn + half * 64 + (c & 7) * 8);
            *(uint4*)(sm + arr * 16384 + half * 8192 + SWZ((uint32_t)(row * 128 + (c & 7) * 16))) = v;
        }

        float o[16][4];
        #pragma unroll
        for (int j = 0; j < 16; j++)
            #pragma unroll
            for (int e = 0; e < 4; e++) o[j][e] = 0.0f;
        float rs[2] = { 0.0f, 0.0f };

        #pragma unroll 1
        for (int t = 0; t < nseg; t++) {
            CPA_WAIT(0);
            __syncthreads();
            if ((t + 1 < nseg) || (seg == 0)) {
                at_stage(sb, b, (t + 1 < nseg) ? t + 1 : 0, (gi + 1) & 1, tid);
                CPA_COMMIT();
            }
            const uint32_t stg = sb + AT_STG0 + (uint32_t)(gi & 1) * 65536u;

            // ---- S = Q K^T : 16 rows x 32 keys, 3 accumulator sets ----
            float shh[4][4], slh[4][4], shl[4][4];
            #pragma unroll
            for (int g = 0; g < 4; g++)
                #pragma unroll
                for (int e = 0; e < 4; e++) { shh[g][e] = 0.f; slh[g][e] = 0.f; shl[g][e] = 0.f; }

            #pragma unroll
            for (int kk = 0; kk < 8; kk++) {
                uint32_t hb = (uint32_t)(kk >> 2) * 8192u;
                int bc = (kk & 3) * 32;
                uint32_t aH[4], aL[4], bHa[4], bHb[4], bLa[4], bLb[4];
                ldsm4(aH,  aAddr(sb + hb,           mw * 16, bc, lane));
                ldsm4(aL,  aAddr(sb + 16384u + hb,  mw * 16, bc, lane));
                ldsm4(bHa, bAddr(stg + hb,          nw * 32,      bc, lane));
                ldsm4(bHb, bAddr(stg + hb,          nw * 32 + 16, bc, lane));
                ldsm4(bLa, bAddr(stg + 16384u + hb, nw * 32,      bc, lane));
                ldsm4(bLb, bAddr(stg + 16384u + hb, nw * 32 + 16, bc, lane));
                mma_bf16(shh[0], aH, bHa[0], bHa[1]);
                mma_bf16(shh[1], aH, bHa[2], bHa[3]);
                mma_bf16(shh[2], aH, bHb[0], bHb[1]);
                mma_bf16(shh[3], aH, bHb[2], bHb[3]);
                mma_bf16(slh[0], aL, bHa[0], bHa[1]);
                mma_bf16(slh[1], aL, bHa[2], bHa[3]);
                mma_bf16(slh[2], aL, bHb[0], bHb[1]);
                mma_bf16(slh[3], aL, bHb[2], bHb[3]);
                mma_bf16(shl[0], aH, bLa[0], bLa[1]);
                mma_bf16(shl[1], aH, bLa[2], bLa[3]);
                mma_bf16(shl[2], aH, bLb[0], bLb[1]);
                mma_bf16(shl[3], aH, bLb[2], bLb[3]);
            }

            // ---- softmax in registers (max-free) ----
            float pr[4][4];
            const int lim0 = q0 + mw * 16 + rq;
            const int lim1 = lim0 + 8;
            #pragma unroll
            for (int g = 0; g < 4; g++) {
                int j = t * 64 + nw * 32 + g * 8 + cq;
                float z0 = shh[g][0] + slh[g][0] + shl[g][0];
                float z1 = shh[g][1] + slh[g][1] + shl[g][1];
                float z2 = shh[g][2] + slh[g][2] + shl[g][2];
                float z3 = shh[g][3] + slh[g][3] + shl[g][3];
                float p0 = (j     <= lim0) ? __expf(z0 * scale) : 0.0f;
                float p1 = (j + 1 <= lim0) ? __expf(z1 * scale) : 0.0f;
                float p2 = (j     <= lim1) ? __expf(z2 * scale) : 0.0f;
                float p3 = (j + 1 <= lim1) ? __expf(z3 * scale) : 0.0f;
                pr[g][0] = p0; pr[g][1] = p1; pr[g][2] = p2; pr[g][3] = p3;
                rs[0] += p0 + p1;
                rs[1] += p2 + p3;
            }
            uint32_t aPh[2][4], aPl[2][4];
            #pragma unroll
            for (int kg = 0; kg < 2; kg++) {
                split2(pr[2 * kg][0],     pr[2 * kg][1],     aPh[kg][0], aPl[kg][0]);
                split2(pr[2 * kg][2],     pr[2 * kg][3],     aPh[kg][1], aPl[kg][1]);
                split2(pr[2 * kg + 1][0], pr[2 * kg + 1][1], aPh[kg][2], aPl[kg][2]);
                split2(pr[2 * kg + 1][2], pr[2 * kg + 1][3], aPh[kg][3], aPl[kg][3]);
            }

            // ---- O += P V over all 128 h-cols ----
            #pragma unroll
            for (int kg = 0; kg < 2; kg++) {
                #pragma unroll
                for (int hb = 0; hb < 8; hb++) {
                    uint32_t bH[4], bL[4];
                    ldsm4t(bH, vAddr(stg + 32768u, hb * 16, nw * 32 + kg * 16, lane));
                    ldsm4t(bL, vAddr(stg + 49152u, hb * 16, nw * 32 + kg * 16, lane));
                    mma_bf16(o[2 * hb],     aPh[kg], bH[0], bH[1]);
                    mma_bf16(o[2 * hb + 1], aPh[kg], bH[2], bH[3]);
                    mma_bf16(o[2 * hb],     aPl[kg], bH[0], bH[1]);
                    mma_bf16(o[2 * hb + 1], aPl[kg], bH[2], bH[3]);
                    mma_bf16(o[2 * hb],     aPh[kg], bL[0], bL[1]);
                    mma_bf16(o[2 * hb + 1], aPh[kg], bL[2], bL[3]);
                }
            }
            gi++;
        }

        // ---- segment epilogue ----
        float r0 = rs[0];
        r0 += __shfl_xor_sync(0xffffffffu, r0, 1);
        r0 += __shfl_xor_sync(0xffffffffu, r0, 2);
        float r1 = rs[1];
        r1 += __shfl_xor_sync(0xffffffffu, r1, 1);
        r1 += __shfl_xor_sync(0xffffffffu, r1, 2);

        float* opart = (float*)(sm + AT_OPART + mw * 8192);
        if (nw == 1) {
            #pragma unroll
            for (int j = 0; j < 16; j++) {
                int col = (j >> 1) * 16 + (j & 1) * 8 + cq;
                *(float2*)(opart + rq * 128 + col)       = make_float2(o[j][0], o[j][1]);
                *(float2*)(opart + (rq + 8) * 128 + col) = make_float2(o[j][2], o[j][3]);
            }
            if ((lane & 3) == 0) {
                lpart[mw * 16 + rq] = r0;
                lpart[mw * 16 + rq + 8] = r1;
            }
        }
        __syncthreads();
        if (nw == 0) {
            float inv0 = 1.0f / (r0 + lpart[mw * 16 + rq]);
            float inv1 = 1.0f / (r1 + lpart[mw * 16 + rq + 8]);
            float* op = out + ((size_t)(b * Tn + q0 + mw * 16)) * Hn;
            #pragma unroll
            for (int j = 0; j < 16; j++) {
                int col = (j >> 1) * 16 + (j & 1) * 8 + cq;
                float2 q0v = *(float2*)(opart + rq * 128 + col);
                float2 q1v = *(float2*)(opart + (rq + 8) * 128 + col);
                *(float2*)(op + (size_t)rq * Hn + col) =
                    make_float2((o[j][0] + q0v.x) * inv0, (o[j][1] + q0v.y) * inv0);
                *(float2*)(op + (size_t)(rq + 8) * Hn + col) =
                    make_float2((o[j][2] + q1v.x) * inv1, (o[j][3] + q1v.y) * inv1);
            }
        }
        __syncthreads();
    }
}

extern "C" void kernel_launch(void* const* d_in, const int* in_sizes, int n_in,
                              void* d_out, int out_size)
{
    const float* x  = (const float*)d_in[0];
    const float* Wq = (const float*)d_in[1];
    const float* Wk = (const float*)d_in[2];
    const float* Wv = (const float*)d_in[3];
    float* out = (float*)d_out;

    cudaFuncSetAttribute(proj_mma, cudaFuncAttributeMaxDynamicSharedMemorySize, PJ_SMEM);
    cudaFuncSetAttribute(attn_mma, cudaFuncAttributeMaxDynamicSharedMemorySize, AT_SMEM);

    convW<<<1536, 256>>>(Wq, Wk, Wv);
    convX<<<BT * Cn / 512, 256>>>(x);
    proj_mma<<<dim3(BT / 64, 3), 256, PJ_SMEM>>>();
    attn_mma<<<dim3(Tn / 128, Bn), 256, AT_SMEM>>>(out);
}

// round 17
// speedup vs baseline: 1.1792x; 1.0481x over previous
#include <cuda_runtime.h>
#include <cuda_bf16.h>
#include <cstdint>
#include <math.h>

#define Bn 8
#define Tn 2048
#define Cn 1024
#define Hn 128
#define BT (Bn * Tn)

// bf16 hi/lo scratch (device globals, no allocation)
__device__ __nv_bfloat16 g_Qh[BT * Hn], g_Ql[BT * Hn];
__device__ __nv_bfloat16 g_Kh[BT * Hn], g_Kl[BT * Hn];
__device__ __nv_bfloat16 g_Vh[BT * Hn], g_Vl[BT * Hn];
__device__ __nv_bfloat16 g_Wh[3 * Hn * Cn], g_Wl[3 * Hn * Cn];  // [o][n][k]
__device__ __nv_bfloat16 g_Xh[BT * Cn], g_Xl[BT * Cn];          // [m][k]
__device__ int g_done[Bn];                                       // proj CTAs retired per batch

// ---------------- helpers ----------------
#define SWZ(x) ((x) ^ (((x) >> 3) & 0x70))

__device__ __forceinline__ uint32_t smem_u32(const void* p) {
    uint32_t a;
    asm("{ .reg .u64 t; cvta.to.shared.u64 t, %1; cvt.u32.u64 %0, t; }" : "=r"(a) : "l"(p));
    return a;
}
__device__ __forceinline__ uint32_t pack2(float lo, float hi) {
    uint32_t r;
    asm("cvt.rn.bf16x2.f32 %0, %1, %2;" : "=r"(r) : "f"(hi), "f"(lo));
    return r;
}
__device__ __forceinline__ void split2(float a, float b, uint32_t& h, uint32_t& l) {
    float ah = __bfloat162float(__float2bfloat16(a));
    float bh = __bfloat162float(__float2bfloat16(b));
    h = pack2(ah, bh);
    l = pack2(a - ah, b - bh);
}
__device__ __forceinline__ void ldsm4(uint32_t* r, uint32_t addr) {
    asm volatile("ldmatrix.sync.aligned.m8n8.x4.shared.b16 {%0,%1,%2,%3}, [%4];"
                 : "=r"(r[0]), "=r"(r[1]), "=r"(r[2]), "=r"(r[3]) : "r"(addr));
}
__device__ __forceinline__ void ldsm4t(uint32_t* r, uint32_t addr) {
    asm volatile("ldmatrix.sync.aligned.m8n8.x4.trans.shared.b16 {%0,%1,%2,%3}, [%4];"
                 : "=r"(r[0]), "=r"(r[1]), "=r"(r[2]), "=r"(r[3]) : "r"(addr));
}
__device__ __forceinline__ void mma_bf16(float* d, const uint32_t* a, uint32_t b0, uint32_t b1) {
    asm volatile("mma.sync.aligned.m16n8k16.row.col.f32.bf16.bf16.f32 "
                 "{%0,%1,%2,%3}, {%4,%5,%6,%7}, {%8,%9}, {%0,%1,%2,%3};"
                 : "+f"(d[0]), "+f"(d[1]), "+f"(d[2]), "+f"(d[3])
                 : "r"(a[0]), "r"(a[1]), "r"(a[2]), "r"(a[3]), "r"(b0), "r"(b1));
}
__device__ __forceinline__ uint32_t aAddr(uint32_t base, int r0, int bc, int lane) {
    int r = r0 + (lane & 15);
    int c = bc + ((lane >> 4) << 4);
    return base + SWZ((uint32_t)(r * 128 + c));
}
__device__ __forceinline__ uint32_t bAddr(uint32_t base, int n0, int bc, int lane) {
    int r = n0 + (lane & 7) + ((lane >> 4) << 3);
    int c = bc + (((lane >> 3) & 1) << 4);
    return base + SWZ((uint32_t)(r * 128 + c));
}
// B-operand x4 via trans from row-major V[k][n]: two 8K col-blocks (n>=64)
__device__ __forceinline__ uint32_t vAddr(uint32_t base, int n0, int k0, int lane) {
    int g = lane >> 3, li = lane & 7;
    int kr = k0 + ((g & 1) << 3) + li;
    int nc = n0 + ((g >> 1) << 3);
    return base + ((uint32_t)(nc >> 6) << 13) + SWZ((uint32_t)(kr * 128 + (nc & 63) * 2));
}
__device__ __forceinline__ void cpa16(uint32_t dst, const void* src) {
    asm volatile("cp.async.cg.shared.global [%0], [%1], 16;" :: "r"(dst), "l"(src));
}
#define CPA_COMMIT() asm volatile("cp.async.commit_group;" ::: "memory")
#define CPA_WAIT(n)  asm volatile("cp.async.wait_group %0;" :: "n"(n) : "memory")

// ============================================================================
// prep: convW (blocks 0..1535) + convX (blocks 1536..34303) + flag zeroing.
// Single launch; both halves run concurrently.
// ============================================================================
__global__ void prep(const float* __restrict__ x, const float* __restrict__ Wq,
                     const float* __restrict__ Wk, const float* __restrict__ Wv) {
    if (blockIdx.x < 1536) {
        if (blockIdx.x == 0 && threadIdx.x < Bn) g_done[threadIdx.x] = 0;
        int idx = blockIdx.x * 256 + threadIdx.x;
        int o = idx >> 17, rem = idx & 131071;
        int k = rem >> 7, n = rem & 127;
        const float* W = o == 0 ? Wq : o == 1 ? Wk : Wv;
        float f = W[(size_t)k * Hn + n];
        __nv_bfloat16 h = __float2bfloat16(f);
        size_t dst = ((size_t)o * Hn + n) * Cn + k;
        g_Wh[dst] = h;
        g_Wl[dst] = __float2bfloat16(f - __bfloat162float(h));
    } else {
        size_t idx = (size_t)(blockIdx.x - 1536) * 256 + threadIdx.x;  // BT*Cn/2
        float2 v = *(const float2*)(x + 2 * idx);
        uint32_t h, l;
        split2(v.x, v.y, h, l);
        *(uint32_t*)((char*)g_Xh + 4 * idx) = h;
        *(uint32_t*)((char*)g_Xl + 4 * idx) = l;
    }
}

// ============================================================================
// Fused proj+attn: 512 CTAs, 512 threads.
//   blockIdx.x <  384 : proj item, batch-major (b = idx/48; 16 m-tiles x 3 o)
//   blockIdx.x >= 384 : attn item, batch-major (b = (idx-384)/16; diag pair)
// Proj CTAs release g_done[b]; attn CTAs acquire (spin). CTA scheduler places
// blocks in index order, so every attn CTA's producers precede it -> no deadlock.
// smem = max(proj 128KB+, attn 176KB+) = attn layout.
// ============================================================================
#define AT_STG0 32768
#define AT_PH   163840
#define AT_PL   172032
#define AT_LS   180224
#define FS_SMEM (180224 + 256 + 128)

__device__ __forceinline__ void pj_stage(uint32_t sb, int m0, int o, int kc, int tid) {
    uint32_t stg = sb + (uint32_t)(kc & 1) * 65536u;
    #pragma unroll
    for (int arr = 0; arr < 4; arr++) {
        const __nv_bfloat16* src =
            arr == 0 ? g_Xh : arr == 1 ? g_Xl : arr == 2 ? g_Wh : g_Wl;
        uint32_t dbase = stg + (uint32_t)arr * 16384u;
        #pragma unroll
        for (int i = 0; i < 2; i++) {
            int id = tid * 2 + i;                 // 0..1023
            int row = id >> 3, c = id & 7;        // 128 rows x 8 chunks
            size_t g = (arr < 2)
                ? ((size_t)(m0 + row) * Cn + kc * 64 + c * 8)
                : (((size_t)o * Hn + row) * Cn + kc * 64 + c * 8);
            cpa16(dbase + SWZ((uint32_t)(row * 128 + c * 16)), src + g);
        }
    }
}

__device__ __forceinline__ void at_stage(uint32_t sb, int b, int t, int s, int tid) {
    uint32_t stg = sb + AT_STG0 + (uint32_t)s * 65536u;
    #pragma unroll
    for (int arr = 0; arr < 4; arr++) {
        const __nv_bfloat16* src =
            arr == 0 ? g_Kh : arr == 1 ? g_Kl : arr == 2 ? g_Vh : g_Vl;
        uint32_t dbase = stg + (uint32_t)arr * 16384u;
        #pragma unroll
        for (int i = 0; i < 2; i++) {
            int id = tid * 2 + i;                 // 0..1023
            int row = id >> 4, c = id & 15;       // 64 rows x 16 chunks
            size_t g = (size_t)(b * Tn + t * 64 + row) * Hn + c * 8;
            uint32_t dst = dbase + ((c >= 8) ? 8192u : 0u)
                         + SWZ((uint32_t)(row * 128 + (c & 7) * 16));
            cpa16(dst, src + g);
        }
    }
}

__global__ __launch_bounds__(512, 1) void fused(float* __restrict__ out) {
    extern __shared__ char smraw[];
    char* sm = (char*)(((uintptr_t)smraw + 127) & ~(uintptr_t)127);
    const uint32_t sb = smem_u32(sm);
    const int tid = threadIdx.x, lane = tid & 31, wid = tid >> 5;
    const int rq = lane >> 2, cq = (lane & 3) * 2;

    if (blockIdx.x < 384) {
        // ==================== PROJ phase (R10-proven) ====================
        const int item = blockIdx.x;
        const int b = item / 48, rem = item % 48;
        const int m0 = (b * 16 + rem / 3) * 128, o = rem % 3;
        const int mw = wid >> 2, nww = wid & 3;

        float d[2][4][4];
        #pragma unroll
        for (int i = 0; i < 2; i++)
            #pragma unroll
            for (int j = 0; j < 4; j++)
                #pragma unroll
                for (int e = 0; e < 4; e++) d[i][j][e] = 0.0f;

        pj_stage(sb, m0, o, 0, tid);
        CPA_COMMIT();

        for (int kc = 0; kc < 16; kc++) {
            if (kc + 1 < 16) { pj_stage(sb, m0, o, kc + 1, tid); CPA_COMMIT(); CPA_WAIT(1); }
            else CPA_WAIT(0);
            __syncthreads();

            const uint32_t stg = sb + (uint32_t)(kc & 1) * 65536u;
            #pragma unroll
            for (int kk = 0; kk < 4; kk++) {
                int bc = kk * 32;
                uint32_t aH[2][4], aL[2][4];
                #pragma unroll
                for (int mt = 0; mt < 2; mt++) {
                    ldsm4(aH[mt], aAddr(stg, mw * 32 + mt * 16, bc, lane));
                    ldsm4(aL[mt], aAddr(stg + 16384u, mw * 32 + mt * 16, bc, lane));
                }
                #pragma unroll
                for (int p2 = 0; p2 < 2; p2++) {
                    uint32_t bH[4], bL[4];
                    ldsm4(bH, bAddr(stg + 32768u, nww * 32 + p2 * 16, bc, lane));
                    ldsm4(bL, bAddr(stg + 49152u, nww * 32 + p2 * 16, bc, lane));
                    #pragma unroll
                    for (int mt = 0; mt < 2; mt++) {
                        float* d0 = d[mt][p2 * 2];
                        float* d1 = d[mt][p2 * 2 + 1];
                        mma_bf16(d0, aH[mt], bH[0], bH[1]);
                        mma_bf16(d1, aH[mt], bH[2], bH[3]);
                        mma_bf16(d0, aL[mt], bH[0], bH[1]);
                        mma_bf16(d1, aL[mt], bH[2], bH[3]);
                        mma_bf16(d0, aH[mt], bL[0], bL[1]);
                        mma_bf16(d1, aH[mt], bL[2], bL[3]);
                    }
                }
            }
            __syncthreads();
        }

        __nv_bfloat16* oh = o == 0 ? g_Qh : o == 1 ? g_Kh : g_Vh;
        __nv_bfloat16* ol = o == 0 ? g_Ql : o == 1 ? g_Kl : g_Vl;
        #pragma unroll
        for (int mt = 0; mt < 2; mt++)
            #pragma unroll
            for (int h = 0; h < 2; h++) {
                int r = m0 + mw * 32 + mt * 16 + rq + h * 8;
                #pragma unroll
                for (int nt = 0; nt < 4; nt++) {
                    int c = nww * 32 + nt * 8 + cq;
                    uint32_t hw, lw;
                    split2(d[mt][nt][h * 2], d[mt][nt][h * 2 + 1], hw, lw);
                    size_t byt = ((size_t)r * Hn + c) * 2;
                    *(uint32_t*)((char*)oh + byt) = hw;
                    *(uint32_t*)((char*)ol + byt) = lw;
                }
            }

        // release: all stores above, device-visible, then count
        __syncthreads();
        if (tid == 0) {
            __threadfence();
            atomicAdd(&g_done[b], 1);
        }
        return;
    }

    // ==================== ATTN phase (R10-proven, 512 thr) ====================
    const int aidx = blockIdx.x - 384;
    const int b = aidx >> 4, pr = aidx & 15;
    const int qt[2] = { pr, 31 - pr };
    const int mw = wid >> 2, nw = wid & 3;
    float* ls = (float*)(sm + AT_LS);
    const float scale = 0.08838834764831845f;  // 1/sqrt(128)

    // acquire: wait for this batch's 48 proj CTAs
    if (tid == 0) {
        while (atomicAdd(&g_done[b], 0) < 48) __nanosleep(200);
        __threadfence();
    }
    __syncthreads();

    at_stage(sb, b, 0, 0, tid);   // prefetch (seg0, tile0)
    CPA_COMMIT();

    int gi = 0;
    #pragma unroll 1
    for (int seg = 0; seg < 2; seg++) {
        const int q0 = qt[seg] * 64;
        const int nseg = qt[seg] + 1;
        __syncthreads();          // ls/Q reuse safe after previous epilogue

        // stage Q hi/lo
        #pragma unroll
        for (int i = 0; i < 4; i++) {
            int id = tid * 4 + i;                 // 0..2047
            int arr = id >> 10, rem2 = id & 1023;
            int row = rem2 >> 4, c = rem2 & 15;
            int half = c >> 3;
            const __nv_bfloat16* src = (arr ? g_Ql : g_Qh);
            uint4 v = *(const uint4*)(src + (size_t)(b * Tn + q0 + row) * Hn + half * 64 + (c & 7) * 8);
            *(uint4*)(sm + arr * 16384 + half * 8192 + SWZ((uint32_t)(row * 128 + (c & 7) * 16))) = v;
        }
        if (tid < 64) ls[tid] = 0.0f;

        float o[4][4];
        #pragma unroll
        for (int j = 0; j < 4; j++)
            #pragma unroll
            for (int e = 0; e < 4; e++) o[j][e] = 0.0f;

        #pragma unroll 1
        for (int t = 0; t < nseg; t++) {
            const bool more = (t + 1 < nseg) || (seg == 0);
            if (more) {
                at_stage(sb, b, (t + 1 < nseg) ? t + 1 : 0, (gi + 1) & 1, tid);
                CPA_COMMIT(); CPA_WAIT(1);
            } else CPA_WAIT(0);
            __syncthreads();

            const uint32_t stg = sb + AT_STG0 + (uint32_t)(gi & 1) * 65536u;

            // S = Q K^T, fused 3-product, 3 independent accumulator sets
            float shh[2][4], slh[2][4], shl[2][4];
            #pragma unroll
            for (int g = 0; g < 2; g++)
                #pragma unroll
                for (int e = 0; e < 4; e++) { shh[g][e] = 0.f; slh[g][e] = 0.f; shl[g][e] = 0.f; }

            #pragma unroll
            for (int kk = 0; kk < 8; kk++) {
                uint32_t hb = (uint32_t)(kk >> 2) * 8192u;
                int bc = (kk & 3) * 32;
                uint32_t aH[4], aL[4], bH[4], bL[4];
                ldsm4(aH, aAddr(sb + hb,           mw * 16, bc, lane));
                ldsm4(aL, aAddr(sb + 16384u + hb,  mw * 16, bc, lane));
                ldsm4(bH, bAddr(stg + hb,          nw * 16, bc, lane));
                ldsm4(bL, bAddr(stg + 16384u + hb, nw * 16, bc, lane));
                mma_bf16(shh[0], aH, bH[0], bH[1]);
                mma_bf16(shh[1], aH, bH[2], bH[3]);
                mma_bf16(slh[0], aL, bH[0], bH[1]);
                mma_bf16(slh[1], aL, bH[2], bH[3]);
                mma_bf16(shl[0], aH, bL[0], bL[1]);
                mma_bf16(shl[1], aH, bL[2], bL[3]);
            }

            // max-free softmax + row-sum accumulation
            const int rbase = mw * 16 + rq;
            float rs[2] = { 0.f, 0.f };
            float pr2[2][4];
            #pragma unroll
            for (int g = 0; g < 2; g++)
                #pragma unroll
                for (int h = 0; h < 2; h++) {
                    int r = rbase + h * 8;
                    int j = t * 64 + nw * 16 + g * 8 + cq;
                    int lim = q0 + r;
                    float z0 = shh[g][h * 2] + slh[g][h * 2] + shl[g][h * 2];
                    float z1 = shh[g][h * 2 + 1] + slh[g][h * 2 + 1] + shl[g][h * 2 + 1];
                    float p0 = (j <= lim) ? __expf(z0 * scale) : 0.0f;
                    float p1 = (j + 1 <= lim) ? __expf(z1 * scale) : 0.0f;
                    pr2[g][h * 2] = p0;
                    pr2[g][h * 2 + 1] = p1;
                    rs[h] += p0 + p1;
                }
            #pragma unroll
            for (int h = 0; h < 2; h++) {
                float v = rs[h];
                v += __shfl_xor_sync(0xffffffffu, v, 1);
                v += __shfl_xor_sync(0xffffffffu, v, 2);
                if ((lane & 3) == 0) atomicAdd(&ls[rbase + h * 8], v);
            }
            // P -> smem bf16 hi/lo
            #pragma unroll
            for (int g = 0; g < 2; g++)
                #pragma unroll
                for (int h = 0; h < 2; h++) {
                    int r = rbase + h * 8;
                    int c = nw * 16 + g * 8 + cq;
                    uint32_t hw, lw;
                    split2(pr2[g][h * 2], pr2[g][h * 2 + 1], hw, lw);
                    uint32_t off = SWZ((uint32_t)(r * 128 + c * 2));
                    *(uint32_t*)(sm + AT_PH + off) = hw;
                    *(uint32_t*)(sm + AT_PL + off) = lw;
                }
            __syncthreads();

            // O += P V, fused 3-product (V row-major, B via ldmatrix.trans)
            #pragma unroll
            for (int kk = 0; kk < 4; kk++) {
                int bc = kk * 32;
                uint32_t aH[4], aL[4];
                ldsm4(aH, aAddr(sb + AT_PH, mw * 16, bc, lane));
                ldsm4(aL, aAddr(sb + AT_PL, mw * 16, bc, lane));
                #pragma unroll
                for (int p2 = 0; p2 < 2; p2++) {
                    uint32_t bH[4], bL[4];
                    ldsm4t(bH, vAddr(stg + 32768u, nw * 32 + p2 * 16, kk * 16, lane));
                    ldsm4t(bL, vAddr(stg + 49152u, nw * 32 + p2 * 16, kk * 16, lane));
                    mma_bf16(o[p2 * 2],     aH, bH[0], bH[1]);
                    mma_bf16(o[p2 * 2 + 1], aH, bH[2], bH[3]);
                    mma_bf16(o[p2 * 2],     aL, bH[0], bH[1]);
                    mma_bf16(o[p2 * 2 + 1], aL, bH[2], bH[3]);
                    mma_bf16(o[p2 * 2],     aH, bL[0], bL[1]);
                    mma_bf16(o[p2 * 2 + 1], aH, bL[2], bL[3]);
                }
            }
            __syncthreads();
            gi++;
        }

        // epilogue: normalize, write fp32
        float* op = out + ((size_t)(b * Tn + q0)) * Hn;
        #pragma unroll
        for (int h = 0; h < 2; h++) {
            int r = mw * 16 + rq + h * 8;
            float inv = 1.0f / ls[r];
            #pragma unroll
            for (int nt = 0; nt < 4; nt++) {
                int c = nw * 32 + nt * 8 + cq;
                float2 w = { o[nt][h * 2] * inv, o[nt][h * 2 + 1] * inv };
                *(float2*)(op + (size_t)r * Hn + c) = w;
            }
        }
    }
}

extern "C" void kernel_launch(void* const* d_in, const int* in_sizes, int n_in,
                              void* d_out, int out_size)
{
    const float* x  = (const float*)d_in[0];
    const float* Wq = (const float*)d_in[1];
    const float* Wk = (const float*)d_in[2];
    const float* Wv = (const float*)d_in[3];
    float* out = (float*)d_out;

    cudaFuncSetAttribute(fused, cudaFuncAttributeMaxDynamicSharedMemorySize, FS_SMEM);

    // prep: convW + convX concurrently + flag reset
    prep<<<1536 + BT * Cn / 512, 256>>>(x, Wq, Wk, Wv);
    // fused proj (384 CTAs, batch-major) + attn (128 CTAs, batch-major)
    fused<<<512, 512, FS_SMEM>>>(out);
}